// round 13
// baseline (speedup 1.0000x reference)
#include <cuda_runtime.h>
#include <cuda_fp16.h>
#include <cstdint>

#define N_NODES 50000
#define N_EDGES 800000
#define D_IN    256
#define D_HID   128
#define D_OUT   40

#define SCAN_BLK 256
#define N_PART   ((N_NODES + SCAN_BLK - 1) / SCAN_BLK)   // 196

// ---- persistent scratch (no allocations allowed) ----
__device__ int    g_cnt_in [N_NODES];
__device__ int    g_cnt_out[N_NODES];
__device__ int    g_part   [N_PART];
__device__ int    g_off    [N_NODES + 1];
__device__ int    g_cursor [N_NODES];
__device__ int    g_eidx   [N_EDGES];           // src indices grouped by dst (CSR)
__device__ float  g_nsrc   [N_NODES];
__device__ float  g_ndst   [N_NODES];
__device__ __half g_h0h [(size_t)N_NODES * D_HID];  // x@W1 (UNSCALED, fp16)
__device__ __half g_midh[(size_t)N_NODES * D_HID];  // relu(agg*ndst+b1)*nsrc (fp16)
__device__ __half g_h1h [(size_t)N_NODES * D_OUT];  // mid@W2 (fp16)

// ---------------------------------------------------------------------------
__global__ void k_init() {
    int i = blockIdx.x * blockDim.x + threadIdx.x;
    if (i < N_NODES) { g_cnt_in[i] = 0; g_cnt_out[i] = 0; }
}

// 4 edges per thread via int4
__global__ void k_hist(const int* __restrict__ src, const int* __restrict__ dst) {
    int i = blockIdx.x * blockDim.x + threadIdx.x;
    if (i < N_EDGES / 4) {
        int4 s = reinterpret_cast<const int4*>(src)[i];
        int4 d = reinterpret_cast<const int4*>(dst)[i];
        atomicAdd(&g_cnt_out[s.x], 1); atomicAdd(&g_cnt_out[s.y], 1);
        atomicAdd(&g_cnt_out[s.z], 1); atomicAdd(&g_cnt_out[s.w], 1);
        atomicAdd(&g_cnt_in [d.x], 1); atomicAdd(&g_cnt_in [d.y], 1);
        atomicAdd(&g_cnt_in [d.z], 1); atomicAdd(&g_cnt_in [d.w], 1);
    }
}

// phase 1: per-block sums of cnt_in
__global__ __launch_bounds__(SCAN_BLK) void k_part() {
    __shared__ int sh[SCAN_BLK];
    int idx = blockIdx.x * SCAN_BLK + threadIdx.x;
    int v = (idx < N_NODES) ? g_cnt_in[idx] : 0;
    sh[threadIdx.x] = v;
    __syncthreads();
    for (int off = SCAN_BLK / 2; off > 0; off >>= 1) {
        if (threadIdx.x < off) sh[threadIdx.x] += sh[threadIdx.x + off];
        __syncthreads();
    }
    if (threadIdx.x == 0) g_part[blockIdx.x] = sh[0];
}

__device__ __forceinline__ int warp_incl_scan(int v, int lane) {
#pragma unroll
    for (int o = 1; o < 32; o <<= 1) {
        int u = __shfl_up_sync(0xffffffffu, v, o);
        if (lane >= o) v += u;
    }
    return v;
}

// phase 2+3 fused, shfl-scan version: redundant scan of the 196 partials,
// in-block exclusive scan of cnt_in, write g_off/g_cursor + norms.
__global__ __launch_bounds__(SCAN_BLK) void k_apply() {
    __shared__ int wsum[8];
    __shared__ int pex[256];
    const int t = threadIdx.x;
    const int lane = t & 31;
    const int w = t >> 5;

    // scan partials (inclusive) into pex
    int pv = (t < N_PART) ? g_part[t] : 0;
    int pi = warp_incl_scan(pv, lane);
    if (lane == 31) wsum[w] = pi;
    __syncthreads();
    if (w == 0) {
        int s = (lane < 8) ? wsum[lane] : 0;
        s = warp_incl_scan(s, lane);
        if (lane < 8) wsum[lane] = s;
    }
    __syncthreads();
    pex[t] = pi + ((w > 0) ? wsum[w - 1] : 0);
    __syncthreads();
    const int block_base = (blockIdx.x > 0) ? pex[blockIdx.x - 1] : 0;

    // local scan of cnt_in
    const int idx = blockIdx.x * SCAN_BLK + t;
    const int cin = (idx < N_NODES) ? g_cnt_in[idx] : 0;
    int li = warp_incl_scan(cin, lane);
    __shared__ int wsum2[8];
    if (lane == 31) wsum2[w] = li;
    __syncthreads();
    if (w == 0) {
        int s = (lane < 8) ? wsum2[lane] : 0;
        s = warp_incl_scan(s, lane);
        if (lane < 8) wsum2[lane] = s;
    }
    __syncthreads();
    int incl = li + ((w > 0) ? wsum2[w - 1] : 0);

    if (idx < N_NODES) {
        int excl = incl - cin + block_base;
        g_off[idx] = excl;
        g_cursor[idx] = excl;
        g_nsrc[idx] = rsqrtf(fmaxf((float)g_cnt_out[idx], 1.0f));
        g_ndst[idx] = rsqrtf(fmaxf((float)cin, 1.0f));
    }
    if (blockIdx.x == 0 && t == 0) g_off[N_NODES] = N_EDGES;
}

// 4 edges per thread via int4
__global__ void k_fill(const int* __restrict__ src, const int* __restrict__ dst) {
    int i = blockIdx.x * blockDim.x + threadIdx.x;
    if (i < N_EDGES / 4) {
        int4 s = reinterpret_cast<const int4*>(src)[i];
        int4 d = reinterpret_cast<const int4*>(dst)[i];
        g_eidx[atomicAdd(&g_cursor[d.x], 1)] = s.x;
        g_eidx[atomicAdd(&g_cursor[d.y], 1)] = s.y;
        g_eidx[atomicAdd(&g_cursor[d.z], 1)] = s.z;
        g_eidx[atomicAdd(&g_cursor[d.w], 1)] = s.w;
    }
}

// ---------------------------------------------------------------------------
__device__ __forceinline__ void mma_f16(float c[4], const uint32_t a[4], const uint32_t b[2]) {
    asm volatile(
        "mma.sync.aligned.m16n8k16.row.col.f32.f16.f16.f32 "
        "{%0,%1,%2,%3}, {%4,%5,%6,%7}, {%8,%9}, {%0,%1,%2,%3};"
        : "+f"(c[0]), "+f"(c[1]), "+f"(c[2]), "+f"(c[3])
        : "r"(a[0]), "r"(a[1]), "r"(a[2]), "r"(a[3]), "r"(b[0]), "r"(b[1]));
}

// GEMM1 (FP16 MMA, fp32 accum): g_h0h[50000,128] = fp16( x @ W1[256,128] )
// smem double-buffered, 2 blocks/SM for cross-block latency hiding.
#define KP_PAD 20
__global__ __launch_bounds__(256, 2) void k_gemm1(const float* __restrict__ x,
                                                  const float* __restrict__ W1) {
    __shared__ __half2 Ah[2][128][KP_PAD];   // [buf][row][kp]
    __shared__ __half2 Bh[2][128][KP_PAD];   // [buf][col][kp]
    const int tid  = threadIdx.x;
    const int wid  = tid >> 5;
    const int lane = tid & 31;
    const int g = lane >> 2;            // 0..7
    const int t = lane & 3;             // 0..3
    const int warp_m = (wid >> 2) * 64; // 0 or 64
    const int warp_n = (wid & 3) * 32;  // 0..96
    const int m0 = blockIdx.x * 128;

    // addressing for the cooperative loads
    const int la_r  = tid >> 1;             // A: row 0..127 (2 threads/row)
    const int la_f4 = (tid & 1) * 4;        // which half of 8 float4s... (handled below)
    (void)la_r; (void)la_f4;

    float c[4][4][4];
#pragma unroll
    for (int mt = 0; mt < 4; mt++)
#pragma unroll
        for (int nt = 0; nt < 4; nt++)
#pragma unroll
            for (int j = 0; j < 4; j++) c[mt][nt][j] = 0.0f;

    // load a chunk (32 k) into buffer `buf`
    auto load_chunk = [&](int k0, int buf) {
#pragma unroll
        for (int tt = 0; tt < 4; tt++) {
            int linear = tid + tt * 256;   // 0..1023
            int r  = linear >> 3;          // row 0..127
            int f4 = linear & 7;           // float4 within 32 k
            int row = m0 + r;
            float4 v = (row < N_NODES)
                ? reinterpret_cast<const float4*>(x + (size_t)row * D_IN + k0)[f4]
                : make_float4(0.f, 0.f, 0.f, 0.f);
            Ah[buf][r][f4 * 2 + 0] = __floats2half2_rn(v.x, v.y);
            Ah[buf][r][f4 * 2 + 1] = __floats2half2_rn(v.z, v.w);
        }
#pragma unroll
        for (int tt = 0; tt < 8; tt++) {
            int linear = tid + tt * 256;   // 0..2047
            int kp = linear >> 7;          // 0..15
            int n  = linear & 127;
            float w0 = W1[(size_t)(k0 + 2 * kp)     * D_HID + n];
            float w1 = W1[(size_t)(k0 + 2 * kp + 1) * D_HID + n];
            Bh[buf][n][kp] = __floats2half2_rn(w0, w1);
        }
    };

    load_chunk(0, 0);
    __syncthreads();

    for (int chunk = 0; chunk < D_IN / 32; chunk++) {
        const int cur = chunk & 1;

        // MMAs on current buffer
#pragma unroll
        for (int ks = 0; ks < 2; ks++) {
            const int kb = ks * 8;
            uint32_t a[4][4], b[4][2];
#pragma unroll
            for (int mt = 0; mt < 4; mt++) {
                int mr = warp_m + mt * 16 + g;
                a[mt][0] = *reinterpret_cast<const uint32_t*>(&Ah[cur][mr    ][kb + t    ]);
                a[mt][1] = *reinterpret_cast<const uint32_t*>(&Ah[cur][mr + 8][kb + t    ]);
                a[mt][2] = *reinterpret_cast<const uint32_t*>(&Ah[cur][mr    ][kb + t + 4]);
                a[mt][3] = *reinterpret_cast<const uint32_t*>(&Ah[cur][mr + 8][kb + t + 4]);
            }
#pragma unroll
            for (int nt = 0; nt < 4; nt++) {
                int n = warp_n + nt * 8 + g;
                b[nt][0] = *reinterpret_cast<const uint32_t*>(&Bh[cur][n][kb + t    ]);
                b[nt][1] = *reinterpret_cast<const uint32_t*>(&Bh[cur][n][kb + t + 4]);
            }
#pragma unroll
            for (int mt = 0; mt < 4; mt++)
#pragma unroll
                for (int nt = 0; nt < 4; nt++)
                    mma_f16(c[mt][nt], a[mt], b[nt]);
        }

        // fill the other buffer for the next chunk
        if (chunk + 1 < D_IN / 32)
            load_chunk((chunk + 1) * 32, cur ^ 1);
        __syncthreads();
    }

    // epilogue -> fp16
#pragma unroll
    for (int mt = 0; mt < 4; mt++) {
        int row0 = m0 + warp_m + mt * 16 + g;
        int row1 = row0 + 8;
#pragma unroll
        for (int nt = 0; nt < 4; nt++) {
            int col = warp_n + nt * 8 + t * 2;
            if (row0 < N_NODES) {
                __half2 v = __floats2half2_rn(c[mt][nt][0], c[mt][nt][1]);
                *reinterpret_cast<__half2*>(g_h0h + (size_t)row0 * D_HID + col) = v;
            }
            if (row1 < N_NODES) {
                __half2 v = __floats2half2_rn(c[mt][nt][2], c[mt][nt][3]);
                *reinterpret_cast<__half2*>(g_h0h + (size_t)row1 * D_HID + col) = v;
            }
        }
    }
}

// ---------------------------------------------------------------------------
// gather-aggregate layer 1, warp-per-node, warp-batched index loading (R12):
// mid[n] = relu( (sum_e h0[src_e]*nsrc[src_e]) * ndst[n] + b1 ) * nsrc[n]
__global__ __launch_bounds__(256) void k_gather1(const float* __restrict__ b1) {
    const int warp = threadIdx.x >> 5;
    const int lane = threadIdx.x & 31;
    const int node = blockIdx.x * 8 + warp;
    if (node >= N_NODES) return;
    const int beg = g_off[node], end = g_off[node + 1];

    float4 a0 = make_float4(0.f, 0.f, 0.f, 0.f);
    float4 a1 = make_float4(0.f, 0.f, 0.f, 0.f);

    for (int base = beg; base < end; base += 32) {
        const int cnt = min(32, end - base);
        int   sidx = 0;
        float sns  = 0.0f;
        if (lane < cnt) {
            sidx = __ldg(&g_eidx[base + lane]);
            sns  = __ldg(&g_nsrc[sidx]);
        }
        int u = 0;
        for (; u + 1 < cnt; u += 2) {
            int   s0 = __shfl_sync(0xffffffffu, sidx, u);
            int   s1 = __shfl_sync(0xffffffffu, sidx, u + 1);
            float n0 = __shfl_sync(0xffffffffu, sns,  u);
            float n1 = __shfl_sync(0xffffffffu, sns,  u + 1);
            uint2 r0 = *reinterpret_cast<const uint2*>(g_h0h + (size_t)s0 * D_HID + lane * 4);
            uint2 r1 = *reinterpret_cast<const uint2*>(g_h0h + (size_t)s1 * D_HID + lane * 4);
            float2 p0a = __half22float2(*reinterpret_cast<const __half2*>(&r0.x));
            float2 p0b = __half22float2(*reinterpret_cast<const __half2*>(&r0.y));
            float2 p1a = __half22float2(*reinterpret_cast<const __half2*>(&r1.x));
            float2 p1b = __half22float2(*reinterpret_cast<const __half2*>(&r1.y));
            a0.x += p0a.x * n0; a0.y += p0a.y * n0; a0.z += p0b.x * n0; a0.w += p0b.y * n0;
            a1.x += p1a.x * n1; a1.y += p1a.y * n1; a1.z += p1b.x * n1; a1.w += p1b.y * n1;
        }
        if (u < cnt) {
            int   s0 = __shfl_sync(0xffffffffu, sidx, u);
            float n0 = __shfl_sync(0xffffffffu, sns,  u);
            uint2 r0 = *reinterpret_cast<const uint2*>(g_h0h + (size_t)s0 * D_HID + lane * 4);
            float2 p0a = __half22float2(*reinterpret_cast<const __half2*>(&r0.x));
            float2 p0b = __half22float2(*reinterpret_cast<const __half2*>(&r0.y));
            a0.x += p0a.x * n0; a0.y += p0a.y * n0; a0.z += p0b.x * n0; a0.w += p0b.y * n0;
        }
    }

    const float nd = g_ndst[node];
    const float ns = g_nsrc[node];
    const float4 bb = reinterpret_cast<const float4*>(b1)[lane];
    float rx = fmaxf((a0.x + a1.x) * nd + bb.x, 0.0f) * ns;
    float ry = fmaxf((a0.y + a1.y) * nd + bb.y, 0.0f) * ns;
    float rz = fmaxf((a0.z + a1.z) * nd + bb.z, 0.0f) * ns;
    float rw = fmaxf((a0.w + a1.w) * nd + bb.w, 0.0f) * ns;
    uint2 o;
    *reinterpret_cast<__half2*>(&o.x) = __floats2half2_rn(rx, ry);
    *reinterpret_cast<__half2*>(&o.y) = __floats2half2_rn(rz, rw);
    *reinterpret_cast<uint2*>(g_midh + (size_t)node * D_HID + lane * 4) = o;
}

// ---------------------------------------------------------------------------
// GEMM2: g_h1h[50000,40] = fp16( g_midh[50000,128] @ W2[128,40] )
__global__ __launch_bounds__(256) void k_gemm2(const float* __restrict__ W2) {
    __shared__ float w2s[D_HID * D_OUT];   // 20 KB, [k][40]
    __shared__ float hs_t[16][132];        // transposed chunk [k][row]
    const int tid = threadIdx.x;
    const int ry = tid >> 3;               // 0..31 -> 4 rows each
    const int cx = tid & 7;                // 0..7  -> 5 cols each
    const int m0 = blockIdx.x * 128;

    for (int i = tid; i < D_HID * D_OUT; i += 256) w2s[i] = W2[i];

    float acc[4][5];
#pragma unroll
    for (int i = 0; i < 4; i++)
#pragma unroll
        for (int j = 0; j < 5; j++) acc[i][j] = 0.0f;

    for (int k0 = 0; k0 < D_HID; k0 += 16) {
        __syncthreads();
#pragma unroll
        for (int t = 0; t < 2; t++) {
            int idx = tid + t * 256;       // 0..511
            int r = idx >> 2;              // row 0..127
            int f4 = idx & 3;              // 4-half group within 16 k
            int row = m0 + r;
            float2 fa = make_float2(0.f, 0.f), fb = make_float2(0.f, 0.f);
            if (row < N_NODES) {
                uint2 v = *reinterpret_cast<const uint2*>(
                    g_midh + (size_t)row * D_HID + k0 + f4 * 4);
                fa = __half22float2(*reinterpret_cast<const __half2*>(&v.x));
                fb = __half22float2(*reinterpret_cast<const __half2*>(&v.y));
            }
            hs_t[f4 * 4 + 0][r] = fa.x;
            hs_t[f4 * 4 + 1][r] = fa.y;
            hs_t[f4 * 4 + 2][r] = fb.x;
            hs_t[f4 * 4 + 3][r] = fb.y;
        }
        __syncthreads();
#pragma unroll
        for (int kk = 0; kk < 16; kk++) {
            float4 a = reinterpret_cast<const float4*>(&hs_t[kk][0])[ry];
            float b[5];
#pragma unroll
            for (int j = 0; j < 5; j++) b[j] = w2s[(k0 + kk) * D_OUT + cx * 5 + j];
#pragma unroll
            for (int j = 0; j < 5; j++) {
                acc[0][j] += a.x * b[j];
                acc[1][j] += a.y * b[j];
                acc[2][j] += a.z * b[j];
                acc[3][j] += a.w * b[j];
            }
        }
    }
#pragma unroll
    for (int i = 0; i < 4; i++) {
        int row = m0 + ry * 4 + i;
        if (row < N_NODES) {
#pragma unroll
            for (int j = 0; j < 5; j++)
                g_h1h[(size_t)row * D_OUT + cx * 5 + j] = __float2half_rn(acc[i][j]);
        }
    }
}

// gather-aggregate layer 2 (fused bias/norm), 20 threads per node, 4-edge unroll
__global__ __launch_bounds__(160) void k_gather2(float* __restrict__ out,
                                                 const float* __restrict__ b2) {
    const int local = threadIdx.x / 20;         // 0..7
    const int c2    = threadIdx.x - local * 20; // 0..19 (channel pair)
    const int node  = blockIdx.x * 8 + local;
    if (node >= N_NODES) return;
    const int beg = g_off[node], end = g_off[node + 1];
    float ax0 = 0.f, ay0 = 0.f, ax1 = 0.f, ay1 = 0.f;
    int i = beg;
    for (; i + 3 < end; i += 4) {
        int s0 = __ldg(&g_eidx[i]);
        int s1 = __ldg(&g_eidx[i + 1]);
        int s2 = __ldg(&g_eidx[i + 2]);
        int s3 = __ldg(&g_eidx[i + 3]);
        uint r0 = *reinterpret_cast<const uint*>(g_h1h + (size_t)s0 * D_OUT + c2 * 2);
        uint r1 = *reinterpret_cast<const uint*>(g_h1h + (size_t)s1 * D_OUT + c2 * 2);
        uint r2 = *reinterpret_cast<const uint*>(g_h1h + (size_t)s2 * D_OUT + c2 * 2);
        uint r3 = *reinterpret_cast<const uint*>(g_h1h + (size_t)s3 * D_OUT + c2 * 2);
        float2 p0 = __half22float2(*reinterpret_cast<const __half2*>(&r0));
        float2 p1 = __half22float2(*reinterpret_cast<const __half2*>(&r1));
        float2 p2 = __half22float2(*reinterpret_cast<const __half2*>(&r2));
        float2 p3 = __half22float2(*reinterpret_cast<const __half2*>(&r3));
        ax0 += p0.x; ay0 += p0.y;
        ax1 += p1.x; ay1 += p1.y;
        ax0 += p2.x; ay0 += p2.y;
        ax1 += p3.x; ay1 += p3.y;
    }
    for (; i < end; i++) {
        int s0 = __ldg(&g_eidx[i]);
        uint r0 = *reinterpret_cast<const uint*>(g_h1h + (size_t)s0 * D_OUT + c2 * 2);
        float2 p0 = __half22float2(*reinterpret_cast<const __half2*>(&r0));
        ax0 += p0.x; ay0 += p0.y;
    }
    const float nd = g_ndst[node];
    float2 bb = *reinterpret_cast<const float2*>(b2 + c2 * 2);
    float2 r;
    r.x = (ax0 + ax1) * nd + bb.x;
    r.y = (ay0 + ay1) * nd + bb.y;
    *reinterpret_cast<float2*>(out + (size_t)node * D_OUT + c2 * 2) = r;
}

// ---------------------------------------------------------------------------
extern "C" void kernel_launch(void* const* d_in, const int* in_sizes, int n_in,
                              void* d_out, int out_size) {
    const float* x   = (const float*)d_in[0];
    const float* W1  = (const float*)d_in[1];
    const float* b1  = (const float*)d_in[2];
    const float* W2  = (const float*)d_in[3];
    const float* b2  = (const float*)d_in[4];
    const int* esrc  = (const int*)d_in[5];
    const int* edst  = (const int*)d_in[6];
    float* out = (float*)d_out;

    const int T = 256;

    // one-time side stream + events (host objects only)
    static cudaStream_t sB = [] { cudaStream_t s; cudaStreamCreateWithFlags(&s, cudaStreamNonBlocking); return s; }();
    static cudaEvent_t evFork = [] { cudaEvent_t e; cudaEventCreateWithFlags(&e, cudaEventDisableTiming); return e; }();
    static cudaEvent_t evJoin = [] { cudaEvent_t e; cudaEventCreateWithFlags(&e, cudaEventDisableTiming); return e; }();

    // fork: CSR build chain on side stream, gemm1 on main stream (independent)
    cudaEventRecord(evFork, 0);
    cudaStreamWaitEvent(sB, evFork, 0);

    k_init<<<(N_NODES + T - 1) / T, T, 0, sB>>>();
    k_hist<<<(N_EDGES / 4 + T - 1) / T, T, 0, sB>>>(esrc, edst);
    k_part<<<N_PART, SCAN_BLK, 0, sB>>>();
    k_apply<<<N_PART, SCAN_BLK, 0, sB>>>();
    k_fill<<<(N_EDGES / 4 + T - 1) / T, T, 0, sB>>>(esrc, edst);
    cudaEventRecord(evJoin, sB);

    k_gemm1<<<(N_NODES + 127) / 128, 256>>>(x, W1);

    // join: gather1 needs both h0 and the CSR/norms
    cudaStreamWaitEvent(0, evJoin, 0);
    k_gather1<<<(N_NODES + 7) / 8, 256>>>(b1);

    // layer 2 (serial chain)
    k_gemm2<<<(N_NODES + 127) / 128, 256>>>(W2);
    k_gather2<<<(N_NODES + 7) / 8, 160>>>(out, b2);
}

// round 14
// speedup vs baseline: 1.0007x; 1.0007x over previous
#include <cuda_runtime.h>
#include <cuda_fp16.h>
#include <cstdint>

#define N_NODES 50000
#define N_EDGES 800000
#define D_IN    256
#define D_HID   128
#define D_OUT   40

#define SCAN_BLK 256
#define N_PART   ((N_NODES + SCAN_BLK - 1) / SCAN_BLK)   // 196

// ---- persistent scratch (no allocations allowed) ----
// NOTE: cnt_in/cnt_out are zero at module load and re-zeroed by k_apply each
// launch (zero-on-consume), so no k_init kernel is needed.
__device__ int    g_cnt_in [N_NODES];
__device__ int    g_cnt_out[N_NODES];
__device__ int    g_part   [N_PART];
__device__ int    g_off    [N_NODES + 1];
__device__ int    g_cursor [N_NODES];
__device__ int    g_eidx   [N_EDGES];           // src indices grouped by dst (CSR)
__device__ float  g_nsrc   [N_NODES];
__device__ float  g_ndst   [N_NODES];
__device__ __half g_h0h [(size_t)N_NODES * D_HID];  // x@W1 (UNSCALED, fp16)
__device__ __half g_midh[(size_t)N_NODES * D_HID];  // relu(agg*ndst+b1)*nsrc (fp16)
__device__ __half g_h1h [(size_t)N_NODES * D_OUT];  // mid@W2 (fp16)

// ---------------------------------------------------------------------------
// 4 edges per thread via int4
__global__ void k_hist(const int* __restrict__ src, const int* __restrict__ dst) {
    int i = blockIdx.x * blockDim.x + threadIdx.x;
    if (i < N_EDGES / 4) {
        int4 s = reinterpret_cast<const int4*>(src)[i];
        int4 d = reinterpret_cast<const int4*>(dst)[i];
        atomicAdd(&g_cnt_out[s.x], 1); atomicAdd(&g_cnt_out[s.y], 1);
        atomicAdd(&g_cnt_out[s.z], 1); atomicAdd(&g_cnt_out[s.w], 1);
        atomicAdd(&g_cnt_in [d.x], 1); atomicAdd(&g_cnt_in [d.y], 1);
        atomicAdd(&g_cnt_in [d.z], 1); atomicAdd(&g_cnt_in [d.w], 1);
    }
}

// phase 1: per-block sums of cnt_in
__global__ __launch_bounds__(SCAN_BLK) void k_part() {
    __shared__ int sh[SCAN_BLK];
    int idx = blockIdx.x * SCAN_BLK + threadIdx.x;
    int v = (idx < N_NODES) ? g_cnt_in[idx] : 0;
    sh[threadIdx.x] = v;
    __syncthreads();
    for (int off = SCAN_BLK / 2; off > 0; off >>= 1) {
        if (threadIdx.x < off) sh[threadIdx.x] += sh[threadIdx.x + off];
        __syncthreads();
    }
    if (threadIdx.x == 0) g_part[blockIdx.x] = sh[0];
}

// phase 2+3 fused (R12 ladder version): every block redundantly scans the 196
// partials, then in-block exclusive scan + writes g_off/g_cursor + norms.
// ALSO resets cnt_in/cnt_out to zero for the next launch (zero-on-consume).
__global__ __launch_bounds__(SCAN_BLK) void k_apply() {
    __shared__ int ps[256];
    __shared__ int sh[SCAN_BLK];
    int t = threadIdx.x;

    ps[t] = (t < N_PART) ? g_part[t] : 0;
    __syncthreads();
    for (int off = 1; off < 256; off <<= 1) {
        int v = 0;
        if (t >= off) v = ps[t - off];
        __syncthreads();
        if (t >= off) ps[t] += v;
        __syncthreads();
    }
    int block_base = (blockIdx.x > 0) ? ps[blockIdx.x - 1] : 0;

    int idx = blockIdx.x * SCAN_BLK + t;
    int cin = (idx < N_NODES) ? g_cnt_in[idx] : 0;
    sh[t] = cin;
    __syncthreads();
    for (int off = 1; off < SCAN_BLK; off <<= 1) {
        int v = 0;
        if (t >= off) v = sh[t - off];
        __syncthreads();
        if (t >= off) sh[t] += v;
        __syncthreads();
    }
    if (idx < N_NODES) {
        int excl = sh[t] - cin + block_base;
        g_off[idx] = excl;
        g_cursor[idx] = excl;
        g_nsrc[idx] = rsqrtf(fmaxf((float)g_cnt_out[idx], 1.0f));
        g_ndst[idx] = rsqrtf(fmaxf((float)cin, 1.0f));
        // zero-on-consume: leave counters ready for the next launch
        g_cnt_in[idx]  = 0;
        g_cnt_out[idx] = 0;
    }
    if (blockIdx.x == 0 && t == 0) g_off[N_NODES] = N_EDGES;
}

// 4 edges per thread via int4
__global__ void k_fill(const int* __restrict__ src, const int* __restrict__ dst) {
    int i = blockIdx.x * blockDim.x + threadIdx.x;
    if (i < N_EDGES / 4) {
        int4 s = reinterpret_cast<const int4*>(src)[i];
        int4 d = reinterpret_cast<const int4*>(dst)[i];
        g_eidx[atomicAdd(&g_cursor[d.x], 1)] = s.x;
        g_eidx[atomicAdd(&g_cursor[d.y], 1)] = s.y;
        g_eidx[atomicAdd(&g_cursor[d.z], 1)] = s.z;
        g_eidx[atomicAdd(&g_cursor[d.w], 1)] = s.w;
    }
}

// ---------------------------------------------------------------------------
__device__ __forceinline__ void mma_f16(float c[4], const uint32_t a[4], const uint32_t b[2]) {
    asm volatile(
        "mma.sync.aligned.m16n8k16.row.col.f32.f16.f16.f32 "
        "{%0,%1,%2,%3}, {%4,%5,%6,%7}, {%8,%9}, {%0,%1,%2,%3};"
        : "+f"(c[0]), "+f"(c[1]), "+f"(c[2]), "+f"(c[3])
        : "r"(a[0]), "r"(a[1]), "r"(a[2]), "r"(a[3]), "r"(b[0]), "r"(b[1]));
}

// GEMM1 (FP16 MMA, fp32 accum): g_h0h[50000,128] = fp16( x @ W1[256,128] )
// R12 version: register prefetch, single smem buffer.
#define KP_PAD 20
__global__ __launch_bounds__(256) void k_gemm1(const float* __restrict__ x,
                                               const float* __restrict__ W1) {
    __shared__ __half2 Ah[128][KP_PAD];   // [row][kp]  kp = k/2 (16 used)
    __shared__ __half2 Bh[128][KP_PAD];   // [col][kp]
    const int tid  = threadIdx.x;
    const int wid  = tid >> 5;
    const int lane = tid & 31;
    const int g = lane >> 2;            // 0..7
    const int t = lane & 3;             // 0..3
    const int warp_m = (wid >> 2) * 64; // 0 or 64
    const int warp_n = (wid & 3) * 32;  // 0..96
    const int m0 = blockIdx.x * 128;

    float c[4][4][4];
#pragma unroll
    for (int mt = 0; mt < 4; mt++)
#pragma unroll
        for (int nt = 0; nt < 4; nt++)
#pragma unroll
            for (int j = 0; j < 4; j++) c[mt][nt][j] = 0.0f;

    float4 pa[4];
    float2 pb[8];

#pragma unroll
    for (int tt = 0; tt < 4; tt++) {
        int linear = tid + tt * 256;
        int r  = linear >> 3;
        int f4 = linear & 7;
        int row = m0 + r;
        pa[tt] = (row < N_NODES)
            ? reinterpret_cast<const float4*>(x + (size_t)row * D_IN)[f4]
            : make_float4(0.f, 0.f, 0.f, 0.f);
    }
#pragma unroll
    for (int tt = 0; tt < 8; tt++) {
        int linear = tid + tt * 256;
        int kp = linear >> 7;
        int n  = linear & 127;
        pb[tt].x = W1[(size_t)(2 * kp)     * D_HID + n];
        pb[tt].y = W1[(size_t)(2 * kp + 1) * D_HID + n];
    }

    for (int chunk = 0; chunk < D_IN / 32; chunk++) {
#pragma unroll
        for (int tt = 0; tt < 4; tt++) {
            int linear = tid + tt * 256;
            int r  = linear >> 3;
            int f4 = linear & 7;
            Ah[r][f4 * 2 + 0] = __floats2half2_rn(pa[tt].x, pa[tt].y);
            Ah[r][f4 * 2 + 1] = __floats2half2_rn(pa[tt].z, pa[tt].w);
        }
#pragma unroll
        for (int tt = 0; tt < 8; tt++) {
            int linear = tid + tt * 256;
            int kp = linear >> 7;
            int n  = linear & 127;
            Bh[n][kp] = __floats2half2_rn(pb[tt].x, pb[tt].y);
        }
        __syncthreads();

        if (chunk + 1 < D_IN / 32) {
            int k0n = (chunk + 1) * 32;
#pragma unroll
            for (int tt = 0; tt < 4; tt++) {
                int linear = tid + tt * 256;
                int r  = linear >> 3;
                int f4 = linear & 7;
                int row = m0 + r;
                pa[tt] = (row < N_NODES)
                    ? reinterpret_cast<const float4*>(x + (size_t)row * D_IN + k0n)[f4]
                    : make_float4(0.f, 0.f, 0.f, 0.f);
            }
#pragma unroll
            for (int tt = 0; tt < 8; tt++) {
                int linear = tid + tt * 256;
                int kp = linear >> 7;
                int n  = linear & 127;
                pb[tt].x = W1[(size_t)(k0n + 2 * kp)     * D_HID + n];
                pb[tt].y = W1[(size_t)(k0n + 2 * kp + 1) * D_HID + n];
            }
        }

#pragma unroll
        for (int ks = 0; ks < 2; ks++) {
            const int kb = ks * 8;
            uint32_t a[4][4], b[4][2];
#pragma unroll
            for (int mt = 0; mt < 4; mt++) {
                int mr = warp_m + mt * 16 + g;
                a[mt][0] = *reinterpret_cast<const uint32_t*>(&Ah[mr    ][kb + t    ]);
                a[mt][1] = *reinterpret_cast<const uint32_t*>(&Ah[mr + 8][kb + t    ]);
                a[mt][2] = *reinterpret_cast<const uint32_t*>(&Ah[mr    ][kb + t + 4]);
                a[mt][3] = *reinterpret_cast<const uint32_t*>(&Ah[mr + 8][kb + t + 4]);
            }
#pragma unroll
            for (int nt = 0; nt < 4; nt++) {
                int n = warp_n + nt * 8 + g;
                b[nt][0] = *reinterpret_cast<const uint32_t*>(&Bh[n][kb + t    ]);
                b[nt][1] = *reinterpret_cast<const uint32_t*>(&Bh[n][kb + t + 4]);
            }
#pragma unroll
            for (int mt = 0; mt < 4; mt++)
#pragma unroll
                for (int nt = 0; nt < 4; nt++)
                    mma_f16(c[mt][nt], a[mt], b[nt]);
        }
        __syncthreads();
    }

#pragma unroll
    for (int mt = 0; mt < 4; mt++) {
        int row0 = m0 + warp_m + mt * 16 + g;
        int row1 = row0 + 8;
#pragma unroll
        for (int nt = 0; nt < 4; nt++) {
            int col = warp_n + nt * 8 + t * 2;
            if (row0 < N_NODES) {
                __half2 v = __floats2half2_rn(c[mt][nt][0], c[mt][nt][1]);
                *reinterpret_cast<__half2*>(g_h0h + (size_t)row0 * D_HID + col) = v;
            }
            if (row1 < N_NODES) {
                __half2 v = __floats2half2_rn(c[mt][nt][2], c[mt][nt][3]);
                *reinterpret_cast<__half2*>(g_h0h + (size_t)row1 * D_HID + col) = v;
            }
        }
    }
}

// ---------------------------------------------------------------------------
// gather-aggregate layer 1, warp-per-node, warp-batched index loading (R12):
// mid[n] = relu( (sum_e h0[src_e]*nsrc[src_e]) * ndst[n] + b1 ) * nsrc[n]
__global__ __launch_bounds__(256) void k_gather1(const float* __restrict__ b1) {
    const int warp = threadIdx.x >> 5;
    const int lane = threadIdx.x & 31;
    const int node = blockIdx.x * 8 + warp;
    if (node >= N_NODES) return;
    const int beg = g_off[node], end = g_off[node + 1];

    float4 a0 = make_float4(0.f, 0.f, 0.f, 0.f);
    float4 a1 = make_float4(0.f, 0.f, 0.f, 0.f);

    for (int base = beg; base < end; base += 32) {
        const int cnt = min(32, end - base);
        int   sidx = 0;
        float sns  = 0.0f;
        if (lane < cnt) {
            sidx = __ldg(&g_eidx[base + lane]);
            sns  = __ldg(&g_nsrc[sidx]);
        }
        int u = 0;
        for (; u + 1 < cnt; u += 2) {
            int   s0 = __shfl_sync(0xffffffffu, sidx, u);
            int   s1 = __shfl_sync(0xffffffffu, sidx, u + 1);
            float n0 = __shfl_sync(0xffffffffu, sns,  u);
            float n1 = __shfl_sync(0xffffffffu, sns,  u + 1);
            uint2 r0 = *reinterpret_cast<const uint2*>(g_h0h + (size_t)s0 * D_HID + lane * 4);
            uint2 r1 = *reinterpret_cast<const uint2*>(g_h0h + (size_t)s1 * D_HID + lane * 4);
            float2 p0a = __half22float2(*reinterpret_cast<const __half2*>(&r0.x));
            float2 p0b = __half22float2(*reinterpret_cast<const __half2*>(&r0.y));
            float2 p1a = __half22float2(*reinterpret_cast<const __half2*>(&r1.x));
            float2 p1b = __half22float2(*reinterpret_cast<const __half2*>(&r1.y));
            a0.x += p0a.x * n0; a0.y += p0a.y * n0; a0.z += p0b.x * n0; a0.w += p0b.y * n0;
            a1.x += p1a.x * n1; a1.y += p1a.y * n1; a1.z += p1b.x * n1; a1.w += p1b.y * n1;
        }
        if (u < cnt) {
            int   s0 = __shfl_sync(0xffffffffu, sidx, u);
            float n0 = __shfl_sync(0xffffffffu, sns,  u);
            uint2 r0 = *reinterpret_cast<const uint2*>(g_h0h + (size_t)s0 * D_HID + lane * 4);
            float2 p0a = __half22float2(*reinterpret_cast<const __half2*>(&r0.x));
            float2 p0b = __half22float2(*reinterpret_cast<const __half2*>(&r0.y));
            a0.x += p0a.x * n0; a0.y += p0a.y * n0; a0.z += p0b.x * n0; a0.w += p0b.y * n0;
        }
    }

    const float nd = g_ndst[node];
    const float ns = g_nsrc[node];
    const float4 bb = reinterpret_cast<const float4*>(b1)[lane];
    float rx = fmaxf((a0.x + a1.x) * nd + bb.x, 0.0f) * ns;
    float ry = fmaxf((a0.y + a1.y) * nd + bb.y, 0.0f) * ns;
    float rz = fmaxf((a0.z + a1.z) * nd + bb.z, 0.0f) * ns;
    float rw = fmaxf((a0.w + a1.w) * nd + bb.w, 0.0f) * ns;
    uint2 o;
    *reinterpret_cast<__half2*>(&o.x) = __floats2half2_rn(rx, ry);
    *reinterpret_cast<__half2*>(&o.y) = __floats2half2_rn(rz, rw);
    *reinterpret_cast<uint2*>(g_midh + (size_t)node * D_HID + lane * 4) = o;
}

// ---------------------------------------------------------------------------
// GEMM2: g_h1h[50000,40] = fp16( g_midh[50000,128] @ W2[128,40] )
__global__ __launch_bounds__(256) void k_gemm2(const float* __restrict__ W2) {
    __shared__ float w2s[D_HID * D_OUT];   // 20 KB, [k][40]
    __shared__ float hs_t[16][132];        // transposed chunk [k][row]
    const int tid = threadIdx.x;
    const int ry = tid >> 3;               // 0..31 -> 4 rows each
    const int cx = tid & 7;                // 0..7  -> 5 cols each
    const int m0 = blockIdx.x * 128;

    for (int i = tid; i < D_HID * D_OUT; i += 256) w2s[i] = W2[i];

    float acc[4][5];
#pragma unroll
    for (int i = 0; i < 4; i++)
#pragma unroll
        for (int j = 0; j < 5; j++) acc[i][j] = 0.0f;

    for (int k0 = 0; k0 < D_HID; k0 += 16) {
        __syncthreads();
#pragma unroll
        for (int t = 0; t < 2; t++) {
            int idx = tid + t * 256;       // 0..511
            int r = idx >> 2;              // row 0..127
            int f4 = idx & 3;              // 4-half group within 16 k
            int row = m0 + r;
            float2 fa = make_float2(0.f, 0.f), fb = make_float2(0.f, 0.f);
            if (row < N_NODES) {
                uint2 v = *reinterpret_cast<const uint2*>(
                    g_midh + (size_t)row * D_HID + k0 + f4 * 4);
                fa = __half22float2(*reinterpret_cast<const __half2*>(&v.x));
                fb = __half22float2(*reinterpret_cast<const __half2*>(&v.y));
            }
            hs_t[f4 * 4 + 0][r] = fa.x;
            hs_t[f4 * 4 + 1][r] = fa.y;
            hs_t[f4 * 4 + 2][r] = fb.x;
            hs_t[f4 * 4 + 3][r] = fb.y;
        }
        __syncthreads();
#pragma unroll
        for (int kk = 0; kk < 16; kk++) {
            float4 a = reinterpret_cast<const float4*>(&hs_t[kk][0])[ry];
            float b[5];
#pragma unroll
            for (int j = 0; j < 5; j++) b[j] = w2s[(k0 + kk) * D_OUT + cx * 5 + j];
#pragma unroll
            for (int j = 0; j < 5; j++) {
                acc[0][j] += a.x * b[j];
                acc[1][j] += a.y * b[j];
                acc[2][j] += a.z * b[j];
                acc[3][j] += a.w * b[j];
            }
        }
    }
#pragma unroll
    for (int i = 0; i < 4; i++) {
        int row = m0 + ry * 4 + i;
        if (row < N_NODES) {
#pragma unroll
            for (int j = 0; j < 5; j++)
                g_h1h[(size_t)row * D_OUT + cx * 5 + j] = __float2half_rn(acc[i][j]);
        }
    }
}

// gather-aggregate layer 2 (fused bias/norm), 20 threads per node, 4-edge unroll
__global__ __launch_bounds__(160) void k_gather2(float* __restrict__ out,
                                                 const float* __restrict__ b2) {
    const int local = threadIdx.x / 20;         // 0..7
    const int c2    = threadIdx.x - local * 20; // 0..19 (channel pair)
    const int node  = blockIdx.x * 8 + local;
    if (node >= N_NODES) return;
    const int beg = g_off[node], end = g_off[node + 1];
    float ax0 = 0.f, ay0 = 0.f, ax1 = 0.f, ay1 = 0.f;
    int i = beg;
    for (; i + 3 < end; i += 4) {
        int s0 = __ldg(&g_eidx[i]);
        int s1 = __ldg(&g_eidx[i + 1]);
        int s2 = __ldg(&g_eidx[i + 2]);
        int s3 = __ldg(&g_eidx[i + 3]);
        uint r0 = *reinterpret_cast<const uint*>(g_h1h + (size_t)s0 * D_OUT + c2 * 2);
        uint r1 = *reinterpret_cast<const uint*>(g_h1h + (size_t)s1 * D_OUT + c2 * 2);
        uint r2 = *reinterpret_cast<const uint*>(g_h1h + (size_t)s2 * D_OUT + c2 * 2);
        uint r3 = *reinterpret_cast<const uint*>(g_h1h + (size_t)s3 * D_OUT + c2 * 2);
        float2 p0 = __half22float2(*reinterpret_cast<const __half2*>(&r0));
        float2 p1 = __half22float2(*reinterpret_cast<const __half2*>(&r1));
        float2 p2 = __half22float2(*reinterpret_cast<const __half2*>(&r2));
        float2 p3 = __half22float2(*reinterpret_cast<const __half2*>(&r3));
        ax0 += p0.x; ay0 += p0.y;
        ax1 += p1.x; ay1 += p1.y;
        ax0 += p2.x; ay0 += p2.y;
        ax1 += p3.x; ay1 += p3.y;
    }
    for (; i < end; i++) {
        int s0 = __ldg(&g_eidx[i]);
        uint r0 = *reinterpret_cast<const uint*>(g_h1h + (size_t)s0 * D_OUT + c2 * 2);
        float2 p0 = __half22float2(*reinterpret_cast<const __half2*>(&r0));
        ax0 += p0.x; ay0 += p0.y;
    }
    const float nd = g_ndst[node];
    float2 bb = *reinterpret_cast<const float2*>(b2 + c2 * 2);
    float2 r;
    r.x = (ax0 + ax1) * nd + bb.x;
    r.y = (ay0 + ay1) * nd + bb.y;
    *reinterpret_cast<float2*>(out + (size_t)node * D_OUT + c2 * 2) = r;
}

// ---------------------------------------------------------------------------
extern "C" void kernel_launch(void* const* d_in, const int* in_sizes, int n_in,
                              void* d_out, int out_size) {
    const float* x   = (const float*)d_in[0];
    const float* W1  = (const float*)d_in[1];
    const float* b1  = (const float*)d_in[2];
    const float* W2  = (const float*)d_in[3];
    const float* b2  = (const float*)d_in[4];
    const int* esrc  = (const int*)d_in[5];
    const int* edst  = (const int*)d_in[6];
    float* out = (float*)d_out;

    const int T = 256;

    // one-time side stream + events (host objects only)
    static cudaStream_t sB = [] { cudaStream_t s; cudaStreamCreateWithFlags(&s, cudaStreamNonBlocking); return s; }();
    static cudaEvent_t evFork = [] { cudaEvent_t e; cudaEventCreateWithFlags(&e, cudaEventDisableTiming); return e; }();
    static cudaEvent_t evJoin = [] { cudaEvent_t e; cudaEventCreateWithFlags(&e, cudaEventDisableTiming); return e; }();

    // fork: CSR build chain on side stream (no k_init — zero-on-consume),
    // gemm1 on main stream (independent)
    cudaEventRecord(evFork, 0);
    cudaStreamWaitEvent(sB, evFork, 0);

    k_hist<<<(N_EDGES / 4 + T - 1) / T, T, 0, sB>>>(esrc, edst);
    k_part<<<N_PART, SCAN_BLK, 0, sB>>>();
    k_apply<<<N_PART, SCAN_BLK, 0, sB>>>();
    k_fill<<<(N_EDGES / 4 + T - 1) / T, T, 0, sB>>>(esrc, edst);
    cudaEventRecord(evJoin, sB);

    k_gemm1<<<(N_NODES + 127) / 128, 256>>>(x, W1);

    // join: gather1 needs both h0 and the CSR/norms
    cudaStreamWaitEvent(0, evJoin, 0);
    k_gather1<<<(N_NODES + 7) / 8, 256>>>(b1);

    // layer 2 (serial chain)
    k_gemm2<<<(N_NODES + 127) / 128, 256>>>(W2);
    k_gather2<<<(N_NODES + 7) / 8, 160>>>(out, b2);
}

// round 15
// speedup vs baseline: 1.0145x; 1.0137x over previous
#include <cuda_runtime.h>
#include <cuda_fp16.h>
#include <cstdint>

#define N_NODES 50000
#define N_EDGES 800000
#define D_IN    256
#define D_HID   128
#define D_OUT   40

#define SCAN_BLK 256
#define N_PART   ((N_NODES + SCAN_BLK - 1) / SCAN_BLK)   // 196

// ---- persistent scratch (no allocations allowed) ----
// cnt_in/cnt_out are zero at module load and re-zeroed by k_apply each launch.
__device__ int    g_cnt_in [N_NODES];
__device__ int    g_cnt_out[N_NODES];
__device__ int    g_rank   [N_EDGES];           // rank of edge within its dst bucket
__device__ int    g_part   [N_PART];
__device__ int    g_off    [N_NODES + 1];
__device__ int    g_eidx   [N_EDGES];           // src indices grouped by dst (CSR)
__device__ float  g_nsrc   [N_NODES];
__device__ float  g_ndst   [N_NODES];
__device__ __half g_h0h [(size_t)N_NODES * D_HID];  // x@W1 (UNSCALED, fp16)
__device__ __half g_midh[(size_t)N_NODES * D_HID];  // relu(agg*ndst+b1)*nsrc (fp16)
__device__ __half g_h1h [(size_t)N_NODES * D_OUT];  // mid@W2 (fp16)

// ---------------------------------------------------------------------------
// hist + rank: cnt_in atomic keeps its return value = edge's rank in dst bucket.
// 4 edges per thread via int4.
__global__ void k_hist(const int* __restrict__ src, const int* __restrict__ dst) {
    int i = blockIdx.x * blockDim.x + threadIdx.x;
    if (i < N_EDGES / 4) {
        int4 s = reinterpret_cast<const int4*>(src)[i];
        int4 d = reinterpret_cast<const int4*>(dst)[i];
        int4 r;
        r.x = atomicAdd(&g_cnt_in[d.x], 1);
        r.y = atomicAdd(&g_cnt_in[d.y], 1);
        r.z = atomicAdd(&g_cnt_in[d.z], 1);
        r.w = atomicAdd(&g_cnt_in[d.w], 1);
        reinterpret_cast<int4*>(g_rank)[i] = r;
        atomicAdd(&g_cnt_out[s.x], 1); atomicAdd(&g_cnt_out[s.y], 1);
        atomicAdd(&g_cnt_out[s.z], 1); atomicAdd(&g_cnt_out[s.w], 1);
    }
}

// phase 1: per-block sums of cnt_in
__global__ __launch_bounds__(SCAN_BLK) void k_part() {
    __shared__ int sh[SCAN_BLK];
    int idx = blockIdx.x * SCAN_BLK + threadIdx.x;
    int v = (idx < N_NODES) ? g_cnt_in[idx] : 0;
    sh[threadIdx.x] = v;
    __syncthreads();
    for (int off = SCAN_BLK / 2; off > 0; off >>= 1) {
        if (threadIdx.x < off) sh[threadIdx.x] += sh[threadIdx.x + off];
        __syncthreads();
    }
    if (threadIdx.x == 0) g_part[blockIdx.x] = sh[0];
}

// phase 2+3 fused: every block redundantly scans the 196 partials, then
// in-block exclusive scan + writes g_off + norms. Resets counters (zero-on-consume).
__global__ __launch_bounds__(SCAN_BLK) void k_apply() {
    __shared__ int ps[256];
    __shared__ int sh[SCAN_BLK];
    int t = threadIdx.x;

    ps[t] = (t < N_PART) ? g_part[t] : 0;
    __syncthreads();
    for (int off = 1; off < 256; off <<= 1) {
        int v = 0;
        if (t >= off) v = ps[t - off];
        __syncthreads();
        if (t >= off) ps[t] += v;
        __syncthreads();
    }
    int block_base = (blockIdx.x > 0) ? ps[blockIdx.x - 1] : 0;

    int idx = blockIdx.x * SCAN_BLK + t;
    int cin = (idx < N_NODES) ? g_cnt_in[idx] : 0;
    sh[t] = cin;
    __syncthreads();
    for (int off = 1; off < SCAN_BLK; off <<= 1) {
        int v = 0;
        if (t >= off) v = sh[t - off];
        __syncthreads();
        if (t >= off) sh[t] += v;
        __syncthreads();
    }
    if (idx < N_NODES) {
        int excl = sh[t] - cin + block_base;
        g_off[idx] = excl;
        g_nsrc[idx] = rsqrtf(fmaxf((float)g_cnt_out[idx], 1.0f));
        g_ndst[idx] = rsqrtf(fmaxf((float)cin, 1.0f));
        g_cnt_in[idx]  = 0;   // zero-on-consume for next launch
        g_cnt_out[idx] = 0;
    }
    if (blockIdx.x == 0 && t == 0) g_off[N_NODES] = N_EDGES;
}

// fill, ATOMIC-FREE: position = off[dst] + rank[edge]. 4 edges per thread.
__global__ void k_fill(const int* __restrict__ src, const int* __restrict__ dst) {
    int i = blockIdx.x * blockDim.x + threadIdx.x;
    if (i < N_EDGES / 4) {
        int4 s = reinterpret_cast<const int4*>(src)[i];
        int4 d = reinterpret_cast<const int4*>(dst)[i];
        int4 r = reinterpret_cast<const int4*>(g_rank)[i];
        g_eidx[__ldg(&g_off[d.x]) + r.x] = s.x;
        g_eidx[__ldg(&g_off[d.y]) + r.y] = s.y;
        g_eidx[__ldg(&g_off[d.z]) + r.z] = s.z;
        g_eidx[__ldg(&g_off[d.w]) + r.w] = s.w;
    }
}

// ---------------------------------------------------------------------------
__device__ __forceinline__ void mma_f16(float c[4], const uint32_t a[4], const uint32_t b[2]) {
    asm volatile(
        "mma.sync.aligned.m16n8k16.row.col.f32.f16.f16.f32 "
        "{%0,%1,%2,%3}, {%4,%5,%6,%7}, {%8,%9}, {%0,%1,%2,%3};"
        : "+f"(c[0]), "+f"(c[1]), "+f"(c[2]), "+f"(c[3])
        : "r"(a[0]), "r"(a[1]), "r"(a[2]), "r"(a[3]), "r"(b[0]), "r"(b[1]));
}

// GEMM1 (FP16 MMA, fp32 accum): g_h0h[50000,128] = fp16( x @ W1[256,128] )
#define KP_PAD 20
__global__ __launch_bounds__(256) void k_gemm1(const float* __restrict__ x,
                                               const float* __restrict__ W1) {
    __shared__ __half2 Ah[128][KP_PAD];   // [row][kp]  kp = k/2 (16 used)
    __shared__ __half2 Bh[128][KP_PAD];   // [col][kp]
    const int tid  = threadIdx.x;
    const int wid  = tid >> 5;
    const int lane = tid & 31;
    const int g = lane >> 2;            // 0..7
    const int t = lane & 3;             // 0..3
    const int warp_m = (wid >> 2) * 64; // 0 or 64
    const int warp_n = (wid & 3) * 32;  // 0..96
    const int m0 = blockIdx.x * 128;

    float c[4][4][4];
#pragma unroll
    for (int mt = 0; mt < 4; mt++)
#pragma unroll
        for (int nt = 0; nt < 4; nt++)
#pragma unroll
            for (int j = 0; j < 4; j++) c[mt][nt][j] = 0.0f;

    float4 pa[4];
    float2 pb[8];

#pragma unroll
    for (int tt = 0; tt < 4; tt++) {
        int linear = tid + tt * 256;
        int r  = linear >> 3;
        int f4 = linear & 7;
        int row = m0 + r;
        pa[tt] = (row < N_NODES)
            ? reinterpret_cast<const float4*>(x + (size_t)row * D_IN)[f4]
            : make_float4(0.f, 0.f, 0.f, 0.f);
    }
#pragma unroll
    for (int tt = 0; tt < 8; tt++) {
        int linear = tid + tt * 256;
        int kp = linear >> 7;
        int n  = linear & 127;
        pb[tt].x = W1[(size_t)(2 * kp)     * D_HID + n];
        pb[tt].y = W1[(size_t)(2 * kp + 1) * D_HID + n];
    }

    for (int chunk = 0; chunk < D_IN / 32; chunk++) {
#pragma unroll
        for (int tt = 0; tt < 4; tt++) {
            int linear = tid + tt * 256;
            int r  = linear >> 3;
            int f4 = linear & 7;
            Ah[r][f4 * 2 + 0] = __floats2half2_rn(pa[tt].x, pa[tt].y);
            Ah[r][f4 * 2 + 1] = __floats2half2_rn(pa[tt].z, pa[tt].w);
        }
#pragma unroll
        for (int tt = 0; tt < 8; tt++) {
            int linear = tid + tt * 256;
            int kp = linear >> 7;
            int n  = linear & 127;
            Bh[n][kp] = __floats2half2_rn(pb[tt].x, pb[tt].y);
        }
        __syncthreads();

        if (chunk + 1 < D_IN / 32) {
            int k0n = (chunk + 1) * 32;
#pragma unroll
            for (int tt = 0; tt < 4; tt++) {
                int linear = tid + tt * 256;
                int r  = linear >> 3;
                int f4 = linear & 7;
                int row = m0 + r;
                pa[tt] = (row < N_NODES)
                    ? reinterpret_cast<const float4*>(x + (size_t)row * D_IN + k0n)[f4]
                    : make_float4(0.f, 0.f, 0.f, 0.f);
            }
#pragma unroll
            for (int tt = 0; tt < 8; tt++) {
                int linear = tid + tt * 256;
                int kp = linear >> 7;
                int n  = linear & 127;
                pb[tt].x = W1[(size_t)(k0n + 2 * kp)     * D_HID + n];
                pb[tt].y = W1[(size_t)(k0n + 2 * kp + 1) * D_HID + n];
            }
        }

#pragma unroll
        for (int ks = 0; ks < 2; ks++) {
            const int kb = ks * 8;
            uint32_t a[4][4], b[4][2];
#pragma unroll
            for (int mt = 0; mt < 4; mt++) {
                int mr = warp_m + mt * 16 + g;
                a[mt][0] = *reinterpret_cast<const uint32_t*>(&Ah[mr    ][kb + t    ]);
                a[mt][1] = *reinterpret_cast<const uint32_t*>(&Ah[mr + 8][kb + t    ]);
                a[mt][2] = *reinterpret_cast<const uint32_t*>(&Ah[mr    ][kb + t + 4]);
                a[mt][3] = *reinterpret_cast<const uint32_t*>(&Ah[mr + 8][kb + t + 4]);
            }
#pragma unroll
            for (int nt = 0; nt < 4; nt++) {
                int n = warp_n + nt * 8 + g;
                b[nt][0] = *reinterpret_cast<const uint32_t*>(&Bh[n][kb + t    ]);
                b[nt][1] = *reinterpret_cast<const uint32_t*>(&Bh[n][kb + t + 4]);
            }
#pragma unroll
            for (int mt = 0; mt < 4; mt++)
#pragma unroll
                for (int nt = 0; nt < 4; nt++)
                    mma_f16(c[mt][nt], a[mt], b[nt]);
        }
        __syncthreads();
    }

#pragma unroll
    for (int mt = 0; mt < 4; mt++) {
        int row0 = m0 + warp_m + mt * 16 + g;
        int row1 = row0 + 8;
#pragma unroll
        for (int nt = 0; nt < 4; nt++) {
            int col = warp_n + nt * 8 + t * 2;
            if (row0 < N_NODES) {
                __half2 v = __floats2half2_rn(c[mt][nt][0], c[mt][nt][1]);
                *reinterpret_cast<__half2*>(g_h0h + (size_t)row0 * D_HID + col) = v;
            }
            if (row1 < N_NODES) {
                __half2 v = __floats2half2_rn(c[mt][nt][2], c[mt][nt][3]);
                *reinterpret_cast<__half2*>(g_h0h + (size_t)row1 * D_HID + col) = v;
            }
        }
    }
}

// ---------------------------------------------------------------------------
// gather-aggregate layer 1, warp-per-node, warp-batched index loading:
// mid[n] = relu( (sum_e h0[src_e]*nsrc[src_e]) * ndst[n] + b1 ) * nsrc[n]
__global__ __launch_bounds__(256) void k_gather1(const float* __restrict__ b1) {
    const int warp = threadIdx.x >> 5;
    const int lane = threadIdx.x & 31;
    const int node = blockIdx.x * 8 + warp;
    if (node >= N_NODES) return;
    const int beg = g_off[node], end = g_off[node + 1];

    float4 a0 = make_float4(0.f, 0.f, 0.f, 0.f);
    float4 a1 = make_float4(0.f, 0.f, 0.f, 0.f);

    for (int base = beg; base < end; base += 32) {
        const int cnt = min(32, end - base);
        int   sidx = 0;
        float sns  = 0.0f;
        if (lane < cnt) {
            sidx = __ldg(&g_eidx[base + lane]);
            sns  = __ldg(&g_nsrc[sidx]);
        }
        int u = 0;
        for (; u + 1 < cnt; u += 2) {
            int   s0 = __shfl_sync(0xffffffffu, sidx, u);
            int   s1 = __shfl_sync(0xffffffffu, sidx, u + 1);
            float n0 = __shfl_sync(0xffffffffu, sns,  u);
            float n1 = __shfl_sync(0xffffffffu, sns,  u + 1);
            uint2 r0 = *reinterpret_cast<const uint2*>(g_h0h + (size_t)s0 * D_HID + lane * 4);
            uint2 r1 = *reinterpret_cast<const uint2*>(g_h0h + (size_t)s1 * D_HID + lane * 4);
            float2 p0a = __half22float2(*reinterpret_cast<const __half2*>(&r0.x));
            float2 p0b = __half22float2(*reinterpret_cast<const __half2*>(&r0.y));
            float2 p1a = __half22float2(*reinterpret_cast<const __half2*>(&r1.x));
            float2 p1b = __half22float2(*reinterpret_cast<const __half2*>(&r1.y));
            a0.x += p0a.x * n0; a0.y += p0a.y * n0; a0.z += p0b.x * n0; a0.w += p0b.y * n0;
            a1.x += p1a.x * n1; a1.y += p1a.y * n1; a1.z += p1b.x * n1; a1.w += p1b.y * n1;
        }
        if (u < cnt) {
            int   s0 = __shfl_sync(0xffffffffu, sidx, u);
            float n0 = __shfl_sync(0xffffffffu, sns,  u);
            uint2 r0 = *reinterpret_cast<const uint2*>(g_h0h + (size_t)s0 * D_HID + lane * 4);
            float2 p0a = __half22float2(*reinterpret_cast<const __half2*>(&r0.x));
            float2 p0b = __half22float2(*reinterpret_cast<const __half2*>(&r0.y));
            a0.x += p0a.x * n0; a0.y += p0a.y * n0; a0.z += p0b.x * n0; a0.w += p0b.y * n0;
        }
    }

    const float nd = g_ndst[node];
    const float ns = g_nsrc[node];
    const float4 bb = reinterpret_cast<const float4*>(b1)[lane];
    float rx = fmaxf((a0.x + a1.x) * nd + bb.x, 0.0f) * ns;
    float ry = fmaxf((a0.y + a1.y) * nd + bb.y, 0.0f) * ns;
    float rz = fmaxf((a0.z + a1.z) * nd + bb.z, 0.0f) * ns;
    float rw = fmaxf((a0.w + a1.w) * nd + bb.w, 0.0f) * ns;
    uint2 o;
    *reinterpret_cast<__half2*>(&o.x) = __floats2half2_rn(rx, ry);
    *reinterpret_cast<__half2*>(&o.y) = __floats2half2_rn(rz, rw);
    *reinterpret_cast<uint2*>(g_midh + (size_t)node * D_HID + lane * 4) = o;
}

// ---------------------------------------------------------------------------
// GEMM2: g_h1h[50000,40] = fp16( g_midh[50000,128] @ W2[128,40] )
__global__ __launch_bounds__(256) void k_gemm2(const float* __restrict__ W2) {
    __shared__ float w2s[D_HID * D_OUT];   // 20 KB, [k][40]
    __shared__ float hs_t[16][132];        // transposed chunk [k][row]
    const int tid = threadIdx.x;
    const int ry = tid >> 3;               // 0..31 -> 4 rows each
    const int cx = tid & 7;                // 0..7  -> 5 cols each
    const int m0 = blockIdx.x * 128;

    for (int i = tid; i < D_HID * D_OUT; i += 256) w2s[i] = W2[i];

    float acc[4][5];
#pragma unroll
    for (int i = 0; i < 4; i++)
#pragma unroll
        for (int j = 0; j < 5; j++) acc[i][j] = 0.0f;

    for (int k0 = 0; k0 < D_HID; k0 += 16) {
        __syncthreads();
#pragma unroll
        for (int t = 0; t < 2; t++) {
            int idx = tid + t * 256;       // 0..511
            int r = idx >> 2;              // row 0..127
            int f4 = idx & 3;              // 4-half group within 16 k
            int row = m0 + r;
            float2 fa = make_float2(0.f, 0.f), fb = make_float2(0.f, 0.f);
            if (row < N_NODES) {
                uint2 v = *reinterpret_cast<const uint2*>(
                    g_midh + (size_t)row * D_HID + k0 + f4 * 4);
                fa = __half22float2(*reinterpret_cast<const __half2*>(&v.x));
                fb = __half22float2(*reinterpret_cast<const __half2*>(&v.y));
            }
            hs_t[f4 * 4 + 0][r] = fa.x;
            hs_t[f4 * 4 + 1][r] = fa.y;
            hs_t[f4 * 4 + 2][r] = fb.x;
            hs_t[f4 * 4 + 3][r] = fb.y;
        }
        __syncthreads();
#pragma unroll
        for (int kk = 0; kk < 16; kk++) {
            float4 a = reinterpret_cast<const float4*>(&hs_t[kk][0])[ry];
            float b[5];
#pragma unroll
            for (int j = 0; j < 5; j++) b[j] = w2s[(k0 + kk) * D_OUT + cx * 5 + j];
#pragma unroll
            for (int j = 0; j < 5; j++) {
                acc[0][j] += a.x * b[j];
                acc[1][j] += a.y * b[j];
                acc[2][j] += a.z * b[j];
                acc[3][j] += a.w * b[j];
            }
        }
    }
#pragma unroll
    for (int i = 0; i < 4; i++) {
        int row = m0 + ry * 4 + i;
        if (row < N_NODES) {
#pragma unroll
            for (int j = 0; j < 5; j++)
                g_h1h[(size_t)row * D_OUT + cx * 5 + j] = __float2half_rn(acc[i][j]);
        }
    }
}

// gather-aggregate layer 2 (fused bias/norm), 20 threads per node, 4-edge unroll
__global__ __launch_bounds__(160) void k_gather2(float* __restrict__ out,
                                                 const float* __restrict__ b2) {
    const int local = threadIdx.x / 20;         // 0..7
    const int c2    = threadIdx.x - local * 20; // 0..19 (channel pair)
    const int node  = blockIdx.x * 8 + local;
    if (node >= N_NODES) return;
    const int beg = g_off[node], end = g_off[node + 1];
    float ax0 = 0.f, ay0 = 0.f, ax1 = 0.f, ay1 = 0.f;
    int i = beg;
    for (; i + 3 < end; i += 4) {
        int s0 = __ldg(&g_eidx[i]);
        int s1 = __ldg(&g_eidx[i + 1]);
        int s2 = __ldg(&g_eidx[i + 2]);
        int s3 = __ldg(&g_eidx[i + 3]);
        uint r0 = *reinterpret_cast<const uint*>(g_h1h + (size_t)s0 * D_OUT + c2 * 2);
        uint r1 = *reinterpret_cast<const uint*>(g_h1h + (size_t)s1 * D_OUT + c2 * 2);
        uint r2 = *reinterpret_cast<const uint*>(g_h1h + (size_t)s2 * D_OUT + c2 * 2);
        uint r3 = *reinterpret_cast<const uint*>(g_h1h + (size_t)s3 * D_OUT + c2 * 2);
        float2 p0 = __half22float2(*reinterpret_cast<const __half2*>(&r0));
        float2 p1 = __half22float2(*reinterpret_cast<const __half2*>(&r1));
        float2 p2 = __half22float2(*reinterpret_cast<const __half2*>(&r2));
        float2 p3 = __half22float2(*reinterpret_cast<const __half2*>(&r3));
        ax0 += p0.x; ay0 += p0.y;
        ax1 += p1.x; ay1 += p1.y;
        ax0 += p2.x; ay0 += p2.y;
        ax1 += p3.x; ay1 += p3.y;
    }
    for (; i < end; i++) {
        int s0 = __ldg(&g_eidx[i]);
        uint r0 = *reinterpret_cast<const uint*>(g_h1h + (size_t)s0 * D_OUT + c2 * 2);
        float2 p0 = __half22float2(*reinterpret_cast<const __half2*>(&r0));
        ax0 += p0.x; ay0 += p0.y;
    }
    const float nd = g_ndst[node];
    float2 bb = *reinterpret_cast<const float2*>(b2 + c2 * 2);
    float2 r;
    r.x = (ax0 + ax1) * nd + bb.x;
    r.y = (ay0 + ay1) * nd + bb.y;
    *reinterpret_cast<float2*>(out + (size_t)node * D_OUT + c2 * 2) = r;
}

// ---------------------------------------------------------------------------
extern "C" void kernel_launch(void* const* d_in, const int* in_sizes, int n_in,
                              void* d_out, int out_size) {
    const float* x   = (const float*)d_in[0];
    const float* W1  = (const float*)d_in[1];
    const float* b1  = (const float*)d_in[2];
    const float* W2  = (const float*)d_in[3];
    const float* b2  = (const float*)d_in[4];
    const int* esrc  = (const int*)d_in[5];
    const int* edst  = (const int*)d_in[6];
    float* out = (float*)d_out;

    const int T = 256;

    // one-time side stream + events (host objects only)
    static cudaStream_t sB = [] { cudaStream_t s; cudaStreamCreateWithFlags(&s, cudaStreamNonBlocking); return s; }();
    static cudaEvent_t evFork = [] { cudaEvent_t e; cudaEventCreateWithFlags(&e, cudaEventDisableTiming); return e; }();
    static cudaEvent_t evJoin = [] { cudaEvent_t e; cudaEventCreateWithFlags(&e, cudaEventDisableTiming); return e; }();

    // fork: CSR build chain on side stream, gemm1 on main stream (independent)
    cudaEventRecord(evFork, 0);
    cudaStreamWaitEvent(sB, evFork, 0);

    k_hist<<<(N_EDGES / 4 + T - 1) / T, T, 0, sB>>>(esrc, edst);
    k_part<<<N_PART, SCAN_BLK, 0, sB>>>();
    k_apply<<<N_PART, SCAN_BLK, 0, sB>>>();
    k_fill<<<(N_EDGES / 4 + T - 1) / T, T, 0, sB>>>(esrc, edst);
    cudaEventRecord(evJoin, sB);

    k_gemm1<<<(N_NODES + 127) / 128, 256>>>(x, W1);

    // join: gather1 needs both h0 and the CSR/norms
    cudaStreamWaitEvent(0, evJoin, 0);
    k_gather1<<<(N_NODES + 7) / 8, 256>>>(b1);

    // layer 2 (serial chain)
    k_gemm2<<<(N_NODES + 127) / 128, 256>>>(W2);
    k_gather2<<<(N_NODES + 7) / 8, 160>>>(out, b2);
}